// round 9
// baseline (speedup 1.0000x reference)
#include <cuda_runtime.h>
#include <cstdint>

// Conv(5x5, SAME) over [256,1,512,512] + FastLIF + FastLI temporal scan.
// Tile 64x16 per block (grid 256), 128 threads, WARP-AUTONOMOUS (no
// __syncthreads): each warp owns a 32x8 quadrant with a private triple-
// buffered smem region filled by its own cp.async (zfill OOB) slots.
// Conv inner product: HYBRID packed math — even horizontal taps (b=0,2,4)
// use fma.rn.f32x2 on register pairs that come DIRECTLY from the LDS.128
// loads (zero packing movs); odd taps (b=1,3) stay scalar FFMA on the
// pair halves. 30% fewer conv issue slots than all-scalar.

#define TT 256
#define HH 512
#define WW 512
#define HW (HH*WW)
#define TW 64        // block tile width
#define THT 16       // block tile height
#define NT 128       // threads per block (4 warps)

#define QW 32        // warp quadrant width (outputs)
#define QH 8         // warp quadrant height (outputs)
#define SWP 40       // warp smem row stride (32+8 halo cols)
#define SHR 12       // warp smem rows (8+4 halo)
#define WBUF (SHR*SWP)        // 480 floats used per buffer
#define WBUFP (WBUF + 4)      // +4 floats per-buffer scratch (zfill dump)
#define F4R 10                // float4 per smem row
#define FILLV (SHR*F4R)       // 120 float4 copies per warp tile
#define PF 4                  // ceil(120/32) fill slots per lane

#define ALPHA_LIF 0.85f
#define V_TH 2.0f
#define ALPHA_LI 0.9f

__device__ __forceinline__ void cp_async16(uint32_t dst_smem, const void* src, int srcsize) {
    asm volatile("cp.async.cg.shared.global [%0], [%1], 16, %2;\n"
                 :: "r"(dst_smem), "l"(src), "r"(srcsize));
}
__device__ __forceinline__ void cp_commit() {
    asm volatile("cp.async.commit_group;\n");
}
__device__ __forceinline__ void cp_wait1() {
    asm volatile("cp.async.wait_group 1;\n");
}

// packed FMA: acc(pair) += wpair * kpair ; operands are float2 lvalues whose
// two floats already sit in adjacent registers (from LDS.128 / float2 init)
__device__ __forceinline__ void fma2p(float2& acc, unsigned long long wpair, float2 kp) {
    asm("fma.rn.f32x2 %0, %1, %2, %0;"
        : "+l"(reinterpret_cast<unsigned long long&>(acc))
        : "l"(wpair), "l"(reinterpret_cast<unsigned long long&>(kp)));
}

__global__ __launch_bounds__(NT, 2)
void snn_fused_kernel(const float* __restrict__ x,
                      const float* __restrict__ kern,
                      float* __restrict__ out)
{
    // [warp][3 buffers][WBUFP floats each]
    __shared__ __align__(16) float sm[4 * 3 * WBUFP];

    const int tid  = threadIdx.x;
    const int w    = tid >> 5;        // warp 0..3
    const int lane = tid & 31;
    const int wx   = w & 1;           // quadrant col (0,1)
    const int wy   = w >> 1;          // quadrant row (0,1)
    const int tc   = lane & 7;        // col group: 4 cols each
    const int rgL  = lane >> 3;       // row-pair group 0..3

    const int x0 = blockIdx.x * TW + QW * wx;   // quadrant origin
    const int y0 = blockIdx.y * THT + QH * wy;

    // 5x5 weights: scalar for odd taps + broadcast (w,w) pairs for even taps
    float wgt[25];
#pragma unroll
    for (int i = 0; i < 25; i++) wgt[i] = __ldg(kern + i);
    unsigned long long wpp[5][3];     // [vertical tap a][b/2 for b=0,2,4]
#pragma unroll
    for (int a = 0; a < 5; a++)
#pragma unroll
        for (int e = 0; e < 3; e++) {
            float wv = wgt[a * 5 + 2 * e];
            float2 p = {wv, wv};
            wpp[a][e] = reinterpret_cast<unsigned long long&>(p);
        }

    // ---- Precompute this lane's PF cp.async fill slots (invariant over t) ----
    // Slot j copies float4 #(lane + j*32) of the 12-row x 10-float4 warp tile.
    // smem col 0 <-> global col x0-4 ; smem row 0 <-> global row y0-2.
    // Inactive slots target the per-buffer scratch at offset WBUF (rotation-safe).
    int soff[PF], goff[PF], ssz[PF];
#pragma unroll
    for (int j = 0; j < PF; j++) {
        int i = lane + j * 32;
        if (i < FILLV) {
            int rr = i / F4R;
            int c4 = i - rr * F4R;
            int gy = y0 - 2 + rr;
            int gx = x0 - 4 + 4 * c4;
            bool v = (gy >= 0) && (gy < HH) && (gx >= 0) && (gx <= WW - 4);
            soff[j] = rr * SWP + 4 * c4;
            goff[j] = v ? (gy * WW + gx) : 0;
            ssz[j]  = v ? 16 : 0;
        } else {
            soff[j] = WBUF;
            goff[j] = 0;
            ssz[j]  = 0;
        }
    }

    // Per-warp buffer base addresses (u32 smem space), rotated each step
    const int wbase = w * 3 * WBUFP;
    uint32_t c0 = (uint32_t)__cvta_generic_to_shared(&sm[wbase]);
    uint32_t c1 = c0 + 4u * WBUFP;
    uint32_t c2 = c0 + 8u * WBUFP;
    int bo = 0;                        // front buffer float-offset within warp region

    // ---- Prefetch timesteps 0 and 1 ----
    {
        const float* xt = x;
#pragma unroll
        for (int j = 0; j < PF; j++) cp_async16(c0 + 4u * soff[j], xt + goff[j], ssz[j]);
        cp_commit();
        xt += HW;
#pragma unroll
        for (int j = 0; j < PF; j++) cp_async16(c1 + 4u * soff[j], xt + goff[j], ssz[j]);
        cp_commit();
    }

    // LIF / LI state: 2 rows x 4 cols
    float s1[8], s2[8];
#pragma unroll
    for (int i = 0; i < 8; i++) { s1[i] = 0.f; s2[i] = 0.f; }

    const float* xp = x + 2 * (size_t)HW;                         // source for t+2
    float* op = out + (size_t)(y0 + 2 * rgL) * WW + x0 + 4 * tc;  // row 0 of pair
    const int rbase = wbase + (2 * rgL) * SWP + 4 * tc;           // smem read base

    for (int t = 0; t < TT; t++) {
        cp_wait1();      // this lane's copies for step t have landed
        __syncwarp();    // other lanes' copies visible

        // Prefetch t+2 into the freed buffer (c2)
        if (t + 2 < TT) {
#pragma unroll
            for (int j = 0; j < PF; j++)
                cp_async16(c2 + 4u * soff[j], xp + goff[j], ssz[j]);
        }
        cp_commit();     // unconditional: uniform wait_group accounting
        xp += HW;

        // ---- 5x5 conv: 2 output rows x 4 cols from 6 streamed input rows ----
        // Row loads: 3x LDS.128; window floats m0..m7 = q0.z..q2.y.
        // Even taps paired: (m0,m1)(m2,m3)(m4,m5)(m6,m7) are native reg pairs.
        const float* rb = &sm[rbase + bo];

        float2 A01 = {0.f, 0.f}, A23 = {0.f, 0.f};   // output row 2rgL
        float2 D01 = {0.f, 0.f}, D23 = {0.f, 0.f};   // output row 2rgL+1
#pragma unroll
        for (int j = 0; j < 6; j++) {
            const float* rp = rb + j * SWP;
            float4 q0 = *(const float4*)(rp + 0);
            float4 q1 = *(const float4*)(rp + 4);
            float4 q2 = *(const float4*)(rp + 8);
            float2 P01 = {q0.z, q0.w};   // (m0,m1)
            float2 P23 = {q1.x, q1.y};   // (m2,m3)
            float2 P45 = {q1.z, q1.w};   // (m4,m5)
            float2 P67 = {q2.x, q2.y};   // (m6,m7)
            if (j < 5) {                     // row 2rgL, vertical tap a=j
                const float* wa = wgt + j * 5;
                // even taps, packed
                fma2p(A01, wpp[j][0], P01);
                fma2p(A01, wpp[j][1], P23);
                fma2p(A01, wpp[j][2], P45);
                fma2p(A23, wpp[j][0], P23);
                fma2p(A23, wpp[j][1], P45);
                fma2p(A23, wpp[j][2], P67);
                // odd taps, scalar on the pair halves
                A01.x = fmaf(wa[1], q0.w, A01.x);  // m1
                A01.y = fmaf(wa[1], q1.x, A01.y);  // m2
                A01.x = fmaf(wa[3], q1.y, A01.x);  // m3
                A01.y = fmaf(wa[3], q1.z, A01.y);  // m4
                A23.x = fmaf(wa[1], q1.y, A23.x);  // m3
                A23.y = fmaf(wa[1], q1.z, A23.y);  // m4
                A23.x = fmaf(wa[3], q1.w, A23.x);  // m5
                A23.y = fmaf(wa[3], q2.x, A23.y);  // m6
            }
            if (j > 0) {                     // row 2rgL+1, vertical tap a=j-1
                const int a = j - 1;
                const float* wb = wgt + a * 5;
                fma2p(D01, wpp[a][0], P01);
                fma2p(D01, wpp[a][1], P23);
                fma2p(D01, wpp[a][2], P45);
                fma2p(D23, wpp[a][0], P23);
                fma2p(D23, wpp[a][1], P45);
                fma2p(D23, wpp[a][2], P67);
                D01.x = fmaf(wb[1], q0.w, D01.x);
                D01.y = fmaf(wb[1], q1.x, D01.y);
                D01.x = fmaf(wb[3], q1.y, D01.x);
                D01.y = fmaf(wb[3], q1.z, D01.y);
                D23.x = fmaf(wb[1], q1.y, D23.x);
                D23.y = fmaf(wb[1], q1.z, D23.y);
                D23.x = fmaf(wb[3], q1.w, D23.x);
                D23.y = fmaf(wb[3], q2.x, D23.y);
            }
        }

        // ---- LIF fire + soft reset, LI readout, two vector stores ----
        float acc[8] = {A01.x, A01.y, A23.x, A23.y,
                        D01.x, D01.y, D23.x, D23.y};
        float o[8];
#pragma unroll
        for (int i = 0; i < 8; i++) {
            float v = fmaf(ALPHA_LIF, s1[i], acc[i]);
            float spk = (v >= V_TH) ? 1.0f : 0.0f;
            s1[i] = fmaf(spk, -V_TH, v);
            s2[i] = fmaf(ALPHA_LI, s2[i], spk);
            o[i] = s2[i];
        }
        float4 o0 = {o[0], o[1], o[2], o[3]};
        float4 o1 = {o[4], o[5], o[6], o[7]};
        *(float4*)op = o0;
        *(float4*)(op + WW) = o1;
        op += HW;

        // Rotate this warp's buffers (addresses and read offset together)
        uint32_t tb = c0; c0 = c1; c1 = c2; c2 = tb;
        bo += WBUFP; if (bo == 3 * WBUFP) bo = 0;
    }
}

extern "C" void kernel_launch(void* const* d_in, const int* in_sizes, int n_in,
                              void* d_out, int out_size)
{
    const float* x = (const float*)d_in[0];
    const float* k = (const float*)d_in[1];
    if (in_sizes[0] == 25) {  // defensive: swap if metadata order differs
        const float* tmp = x; x = k; k = tmp;
    }
    float* out = (float*)d_out;

    dim3 grid(WW / TW, HH / THT);   // 8 x 32 = 256 blocks
    snn_fused_kernel<<<grid, NT>>>(x, k, out);
}

// round 10
// speedup vs baseline: 1.0257x; 1.0257x over previous
#include <cuda_runtime.h>
#include <cstdint>

// Conv(5x5, SAME) over [256,1,512,512] + FastLIF + FastLI temporal scan.
// ONE WARP PER BLOCK: each 32-thread block owns a 32x8 output quadrant for
// all 256 timesteps (grid 16x64 = 1024 blocks -> 6.92/SM, near-perfect FMA
// load balance: crit SM 1792 outputs/step vs 2048 with grid 256).
// Private triple-buffered smem filled by cp.async (zfill OOB), prefetch
// depth 2, sync = cp.async.wait_group + __syncwarp only. Each thread
// computes 2 rows x 4 cols (scalar FFMA); LIF/LI state in registers.

#define TT 256
#define HH 512
#define WW 512
#define HW (HH*WW)

#define QW 32        // block/warp quadrant width (outputs)
#define QH 8         // quadrant height (outputs)
#define NT 32        // threads per block (1 warp)
#define SWP 40       // smem row stride (32+8 halo cols)
#define SHR 12       // smem rows (8+4 halo)
#define WBUF (SHR*SWP)        // 480 floats used per buffer
#define WBUFP (WBUF + 4)      // +4 floats per-buffer scratch (zfill dump)
#define F4R 10                // float4 per smem row
#define FILLV (SHR*F4R)       // 120 float4 copies per tile
#define PF 4                  // ceil(120/32) fill slots per lane

#define ALPHA_LIF 0.85f
#define V_TH 2.0f
#define ALPHA_LI 0.9f

__device__ __forceinline__ void cp_async16(uint32_t dst_smem, const void* src, int srcsize) {
    asm volatile("cp.async.cg.shared.global [%0], [%1], 16, %2;\n"
                 :: "r"(dst_smem), "l"(src), "r"(srcsize));
}
__device__ __forceinline__ void cp_commit() {
    asm volatile("cp.async.commit_group;\n");
}
__device__ __forceinline__ void cp_wait1() {
    asm volatile("cp.async.wait_group 1;\n");
}

__global__ __launch_bounds__(NT)
void snn_fused_kernel(const float* __restrict__ x,
                      const float* __restrict__ kern,
                      float* __restrict__ out)
{
    // 3 buffers of WBUFP floats (per-buffer scratch at offset WBUF)
    __shared__ __align__(16) float sm[3 * WBUFP];

    const int lane = threadIdx.x;
    const int tc   = lane & 7;        // col group: output cols x0+4tc .. +3
    const int rgL  = lane >> 3;       // row-pair group: rows y0+2rgL, +1

    const int x0 = blockIdx.x * QW;
    const int y0 = blockIdx.y * QH;

    // 5x5 weights in registers (uniform broadcast)
    float wgt[25];
#pragma unroll
    for (int i = 0; i < 25; i++) wgt[i] = __ldg(kern + i);

    // ---- Precompute this lane's PF cp.async fill slots (invariant over t) ----
    // Slot j copies float4 #(lane + j*32) of the 12-row x 10-float4 tile.
    // smem col 0 <-> global col x0-4 ; smem row 0 <-> global row y0-2.
    // Inactive slots target the per-buffer scratch at offset WBUF.
    int soff[PF], goff[PF], ssz[PF];
#pragma unroll
    for (int j = 0; j < PF; j++) {
        int i = lane + j * 32;
        if (i < FILLV) {
            int rr = i / F4R;
            int c4 = i - rr * F4R;
            int gy = y0 - 2 + rr;
            int gx = x0 - 4 + 4 * c4;
            bool v = (gy >= 0) && (gy < HH) && (gx >= 0) && (gx <= WW - 4);
            soff[j] = rr * SWP + 4 * c4;
            goff[j] = v ? (gy * WW + gx) : 0;
            ssz[j]  = v ? 16 : 0;
        } else {
            soff[j] = WBUF;   // per-buffer scratch, rotation-safe
            goff[j] = 0;
            ssz[j]  = 0;
        }
    }

    // Buffer base addresses (u32 smem space), rotated each step
    uint32_t c0 = (uint32_t)__cvta_generic_to_shared(&sm[0]);
    uint32_t c1 = c0 + 4u * WBUFP;
    uint32_t c2 = c0 + 8u * WBUFP;
    int bo = 0;                        // front buffer float-offset

    // ---- Prefetch timesteps 0 and 1 ----
    {
        const float* xt = x;
#pragma unroll
        for (int j = 0; j < PF; j++) cp_async16(c0 + 4u * soff[j], xt + goff[j], ssz[j]);
        cp_commit();
        xt += HW;
#pragma unroll
        for (int j = 0; j < PF; j++) cp_async16(c1 + 4u * soff[j], xt + goff[j], ssz[j]);
        cp_commit();
    }

    // LIF / LI state: 2 rows x 4 cols
    float s1[8], s2[8];
#pragma unroll
    for (int i = 0; i < 8; i++) { s1[i] = 0.f; s2[i] = 0.f; }

    const float* xp = x + 2 * (size_t)HW;                         // source for t+2
    float* op = out + (size_t)(y0 + 2 * rgL) * WW + x0 + 4 * tc;  // row 0 of pair
    const int rbase = (2 * rgL) * SWP + 4 * tc;                   // smem read base

    for (int t = 0; t < TT; t++) {
        cp_wait1();      // this lane's copies for step t have landed
        __syncwarp();    // other lanes' copies visible

        // Prefetch t+2 into the freed buffer (c2)
        if (t + 2 < TT) {
#pragma unroll
            for (int j = 0; j < PF; j++)
                cp_async16(c2 + 4u * soff[j], xp + goff[j], ssz[j]);
        }
        cp_commit();     // unconditional: uniform wait_group accounting
        xp += HW;

        // ---- 5x5 conv: 2 output rows x 4 cols from 6 streamed input rows ----
        // Row loads: 3x LDS.128 (conflict-free: 8-lane phase spans one row);
        // window floats m0..m7 = q0.z..q2.y.
        const float* rb = &sm[rbase + bo];

        float a0 = 0.f, a1 = 0.f, a2 = 0.f, a3 = 0.f;   // output row 2rgL
        float d0 = 0.f, d1 = 0.f, d2 = 0.f, d3 = 0.f;   // output row 2rgL+1
#pragma unroll
        for (int j = 0; j < 6; j++) {
            const float* rp = rb + j * SWP;
            float4 q0 = *(const float4*)(rp + 0);
            float4 q1 = *(const float4*)(rp + 4);
            float4 q2 = *(const float4*)(rp + 8);
            float m0 = q0.z, m1 = q0.w, m2 = q1.x, m3 = q1.y;
            float m4 = q1.z, m5 = q1.w, m6 = q2.x, m7 = q2.y;
            if (j < 5) {                     // row 2rgL, vertical tap a=j
                const float* wa = wgt + j * 5;
                a0 = fmaf(wa[0], m0, a0); a0 = fmaf(wa[1], m1, a0);
                a0 = fmaf(wa[2], m2, a0); a0 = fmaf(wa[3], m3, a0);
                a0 = fmaf(wa[4], m4, a0);
                a1 = fmaf(wa[0], m1, a1); a1 = fmaf(wa[1], m2, a1);
                a1 = fmaf(wa[2], m3, a1); a1 = fmaf(wa[3], m4, a1);
                a1 = fmaf(wa[4], m5, a1);
                a2 = fmaf(wa[0], m2, a2); a2 = fmaf(wa[1], m3, a2);
                a2 = fmaf(wa[2], m4, a2); a2 = fmaf(wa[3], m5, a2);
                a2 = fmaf(wa[4], m6, a2);
                a3 = fmaf(wa[0], m3, a3); a3 = fmaf(wa[1], m4, a3);
                a3 = fmaf(wa[2], m5, a3); a3 = fmaf(wa[3], m6, a3);
                a3 = fmaf(wa[4], m7, a3);
            }
            if (j > 0) {                     // row 2rgL+1, vertical tap a=j-1
                const float* wb = wgt + (j - 1) * 5;
                d0 = fmaf(wb[0], m0, d0); d0 = fmaf(wb[1], m1, d0);
                d0 = fmaf(wb[2], m2, d0); d0 = fmaf(wb[3], m3, d0);
                d0 = fmaf(wb[4], m4, d0);
                d1 = fmaf(wb[0], m1, d1); d1 = fmaf(wb[1], m2, d1);
                d1 = fmaf(wb[2], m3, d1); d1 = fmaf(wb[3], m4, d1);
                d1 = fmaf(wb[4], m5, d1);
                d2 = fmaf(wb[0], m2, d2); d2 = fmaf(wb[1], m3, d2);
                d2 = fmaf(wb[2], m4, d2); d2 = fmaf(wb[3], m5, d2);
                d2 = fmaf(wb[4], m6, d2);
                d3 = fmaf(wb[0], m3, d3); d3 = fmaf(wb[1], m4, d3);
                d3 = fmaf(wb[2], m5, d3); d3 = fmaf(wb[3], m6, d3);
                d3 = fmaf(wb[4], m7, d3);
            }
        }

        // ---- LIF fire + soft reset, LI readout, two vector stores ----
        float acc[8] = {a0, a1, a2, a3, d0, d1, d2, d3};
        float o[8];
#pragma unroll
        for (int i = 0; i < 8; i++) {
            float v = fmaf(ALPHA_LIF, s1[i], acc[i]);
            float spk = (v >= V_TH) ? 1.0f : 0.0f;
            s1[i] = fmaf(spk, -V_TH, v);
            s2[i] = fmaf(ALPHA_LI, s2[i], spk);
            o[i] = s2[i];
        }
        float4 o0 = {o[0], o[1], o[2], o[3]};
        float4 o1 = {o[4], o[5], o[6], o[7]};
        *(float4*)op = o0;
        *(float4*)(op + WW) = o1;
        op += HW;

        // Rotate buffers (addresses and read offset together)
        uint32_t tb = c0; c0 = c1; c1 = c2; c2 = tb;
        bo += WBUFP; if (bo == 3 * WBUFP) bo = 0;
    }
}

extern "C" void kernel_launch(void* const* d_in, const int* in_sizes, int n_in,
                              void* d_out, int out_size)
{
    const float* x = (const float*)d_in[0];
    const float* k = (const float*)d_in[1];
    if (in_sizes[0] == 25) {  // defensive: swap if metadata order differs
        const float* tmp = x; x = k; k = tmp;
    }
    float* out = (float*)d_out;

    dim3 grid(WW / QW, HH / QH);   // 16 x 64 = 1024 one-warp blocks
    snn_fused_kernel<<<grid, NT>>>(x, k, out);
}